// round 2
// baseline (speedup 1.0000x reference)
#include <cuda_runtime.h>
#include <cuda_bf16.h>
#include <string.h>

// Problem constants (static shapes from the reference)
#define NPTS   32768          // 8 * 4096 points (i,j flattened, contiguous in output)
#define NROWS  4096           // 64 * 64 (m,n) pairs
#define NBASIS 23

// Scratch: poly[k][p], k-major so GEMM-side loads are coalesced float4.
__device__ float g_poly[NBASIS * NPTS];

// ---------------------------------------------------------------------------
// Kernel 1: per-point hydrogen wavefunction basis (23 values per point).
// All trig eliminated:
//   st*cos(phi) = x/r, st*sin(phi) = y/r,
//   st^2*cos(2phi) = (x^2-y^2)/r^2, st^2*sin(2phi) = 2xy/r^2.
// Radial parts R_{n,l} and real spherical harmonics match the reference's
// generic Laguerre/Legendre construction (Condon–Shortley signs included).
// ---------------------------------------------------------------------------
__global__ void basis_kernel(const float* __restrict__ pos) {
    int p = blockIdx.x * blockDim.x + threadIdx.x;
    if (p >= NPTS) return;

    float x = pos[3 * p + 0];
    float y = pos[3 * p + 1];
    float z = pos[3 * p + 2];

    float r    = sqrtf(x * x + y * y + z * z) + 1e-12f;  // matches reference
    float invr = 1.0f / r;
    float xs = x * invr;          // st*cos(phi)
    float ys = y * invr;          // st*sin(phi)
    float ct = z * invr;

    float e1 = expf(-r);
    float e2 = expf(-0.5f * r);
    float e3 = expf(-r * (1.0f / 3.0f));
    float e4 = expf(-0.25f * r);

    // Spherical-harmonic constants
    const float C00 = 0.28209479177387814f;   // 1/(2 sqrt(pi))
    const float K10 = 0.4886025119029199f;    // sqrt(3/(4 pi))
    const float C21 = 1.0925484305920792f;    // sqrt(15/(4 pi))
    const float C22 = 0.5462742152960396f;    // sqrt(15/(16 pi))
    const float C20 = 0.31539156525252005f;   // 0.5*sqrt(5/(4 pi))

    float Y1m1 = -K10 * ys;
    float Y10  =  K10 * ct;
    float Y1p1 = -K10 * xs;
    float Y2m2 =  C21 * xs * ys;
    float Y2m1 = -C21 * ys * ct;
    float Y20  =  C20 * (3.0f * ct * ct - 1.0f);
    float Y2p1 = -C21 * xs * ct;
    float Y2p2 =  C22 * (xs * xs - ys * ys);

    // Radial parts, rho_n = 2r/n, prefactors sqrt((2/n)^3 (n-l-1)!/(2n (n+l)!))
    float R10 = 2.0f * e1;
    float R20 = 0.35355339059327373f * e2 * (2.0f - r);
    float R21 = 0.2041241452319315f  * e2 * r;

    float rho3 = (2.0f / 3.0f) * r;
    float R30 = 0.1283000598199168f   * e3 * (3.0f - 3.0f * rho3 + 0.5f * rho3 * rho3);
    float R31 = 0.045360921162019494f * e3 * rho3 * (4.0f - rho3);
    float R32 = 0.02028602242947916f  * e3 * rho3 * rho3;

    float rho4 = 0.5f * r;
    float R40 = 0.0625f * e4 *
                (4.0f - 6.0f * rho4 + 2.0f * rho4 * rho4 - rho4 * rho4 * rho4 * (1.0f / 6.0f));
    float R41 = 0.016137430609197573f * e4 * rho4 * (10.0f - 5.0f * rho4 + 0.5f * rho4 * rho4);
    float R42 = 0.004658474194686761f * e4 * rho4 * rho4 * (6.0f - rho4);

    float v[NBASIS];
    v[0]  = R10 * C00;
    v[1]  = R20 * C00;
    v[2]  = R21 * Y1m1;  v[3]  = R21 * Y10;  v[4]  = R21 * Y1p1;
    v[5]  = R30 * C00;
    v[6]  = R31 * Y1m1;  v[7]  = R31 * Y10;  v[8]  = R31 * Y1p1;
    v[9]  = R32 * Y2m2;  v[10] = R32 * Y2m1; v[11] = R32 * Y20;
    v[12] = R32 * Y2p1;  v[13] = R32 * Y2p2;
    v[14] = R40 * C00;
    v[15] = R41 * Y1m1;  v[16] = R41 * Y10;  v[17] = R41 * Y1p1;
    v[18] = R42 * Y2m2;  v[19] = R42 * Y2m1; v[20] = R42 * Y20;
    v[21] = R42 * Y2p1;  v[22] = R42 * Y2p2;

#pragma unroll
    for (int k = 0; k < NBASIS; k++) g_poly[k * NPTS + p] = v[k];
}

// ---------------------------------------------------------------------------
// Kernel 2: out(4096 x 32768) = coeff(4096 x 23) @ poly(23 x 32768)
// Packed-fp32 (fma.rn.f32x2) GEMM. Each thread: 4 consecutive output columns,
// poly held in 23 float4 registers; inner loop over 128 coefficient rows with
// coefficients pre-duplicated to {c,c} float2 in smem (broadcast LDS.64).
// ---------------------------------------------------------------------------
#define TPB  256
#define PT   1024   // points per block  (TPB * 4)
#define RT   128    // coefficient rows per block

__device__ __forceinline__ float2 fma2(float2 a, float2 b, float2 c) {
    unsigned long long ua, ub, uc;
    memcpy(&ua, &a, 8); memcpy(&ub, &b, 8); memcpy(&uc, &c, 8);
    asm("fma.rn.f32x2 %0, %1, %2, %0;" : "+l"(uc) : "l"(ua), "l"(ub));
    float2 d; memcpy(&d, &uc, 8);
    return d;
}

__global__ __launch_bounds__(TPB, 2) void gemm_kernel(const float* __restrict__ coeff,
                                                      float* __restrict__ out) {
    __shared__ float2 cs[RT * NBASIS];

    int tid = threadIdx.x;
    int p0  = blockIdx.x * PT + tid * 4;
    int r0  = blockIdx.y * RT;

    // Cooperative load of the coefficient tile, duplicated into both f32x2 lanes.
    for (int i = tid; i < RT * NBASIS; i += TPB) {
        float c = coeff[r0 * NBASIS + i];
        cs[i] = make_float2(c, c);
    }

    // Poly columns for this thread's 4 points: 23 x float4, lives in registers.
    float4 pv[NBASIS];
#pragma unroll
    for (int k = 0; k < NBASIS; k++)
        pv[k] = *reinterpret_cast<const float4*>(&g_poly[k * NPTS + p0]);

    __syncthreads();

    float* outp = out + (size_t)r0 * NPTS + p0;
#pragma unroll 2
    for (int rr = 0; rr < RT; ++rr) {
        const float2* crow = &cs[rr * NBASIS];
        float2 a0 = make_float2(0.0f, 0.0f);
        float2 a1 = make_float2(0.0f, 0.0f);
#pragma unroll
        for (int k = 0; k < NBASIS; k++) {
            float2 ck = crow[k];                         // broadcast LDS.64
            a0 = fma2(ck, make_float2(pv[k].x, pv[k].y), a0);
            a1 = fma2(ck, make_float2(pv[k].z, pv[k].w), a1);
        }
        float4 o = make_float4(a0.x, a0.y, a1.x, a1.y);
        *reinterpret_cast<float4*>(outp) = o;            // STG.128, coalesced
        outp += NPTS;
    }
}

// ---------------------------------------------------------------------------
// Launch: inputs per metadata order: [0] position (8*4096*3 f32),
//         [1] coefficients (64*64*23 f32). Output: 64*64*8*4096 f32.
// ---------------------------------------------------------------------------
extern "C" void kernel_launch(void* const* d_in, const int* in_sizes, int n_in,
                              void* d_out, int out_size) {
    const float* pos   = (const float*)d_in[0];
    const float* coeff = (const float*)d_in[1];
    float* out = (float*)d_out;

    basis_kernel<<<NPTS / TPB, TPB>>>(pos);

    dim3 grid(NPTS / PT, NROWS / RT);   // (32, 32)
    gemm_kernel<<<grid, TPB>>>(coeff, out);
}

// round 4
// speedup vs baseline: 1.1394x; 1.1394x over previous
#include <cuda_runtime.h>
#include <cuda_bf16.h>
#include <string.h>

// Problem constants (static shapes from the reference)
#define NPTS   32768          // 8 * 4096 points (i,j flattened, contiguous in output)
#define NROWS  4096           // 64 * 64 (m,n) pairs
#define NBASIS 23

// Scratch: poly[k][p], k-major so GEMM-side loads are coalesced float4.
__device__ float g_poly[NBASIS * NPTS];

// ---------------------------------------------------------------------------
// Kernel 1: per-point hydrogen wavefunction basis (23 values per point).
// Trig eliminated: st*cos(phi)=x/r, st*sin(phi)=y/r, etc. Validated round 2
// at rel_err 1.2e-7.
// ---------------------------------------------------------------------------
__global__ void basis_kernel(const float* __restrict__ pos) {
    int p = blockIdx.x * blockDim.x + threadIdx.x;
    if (p >= NPTS) return;

    float x = pos[3 * p + 0];
    float y = pos[3 * p + 1];
    float z = pos[3 * p + 2];

    float r    = sqrtf(x * x + y * y + z * z) + 1e-12f;
    float invr = 1.0f / r;
    float xs = x * invr;
    float ys = y * invr;
    float ct = z * invr;

    float e1 = expf(-r);
    float e2 = expf(-0.5f * r);
    float e3 = expf(-r * (1.0f / 3.0f));
    float e4 = expf(-0.25f * r);

    const float C00 = 0.28209479177387814f;
    const float K10 = 0.4886025119029199f;
    const float C21 = 1.0925484305920792f;
    const float C22 = 0.5462742152960396f;
    const float C20 = 0.31539156525252005f;

    float Y1m1 = -K10 * ys;
    float Y10  =  K10 * ct;
    float Y1p1 = -K10 * xs;
    float Y2m2 =  C21 * xs * ys;
    float Y2m1 = -C21 * ys * ct;
    float Y20  =  C20 * (3.0f * ct * ct - 1.0f);
    float Y2p1 = -C21 * xs * ct;
    float Y2p2 =  C22 * (xs * xs - ys * ys);

    float R10 = 2.0f * e1;
    float R20 = 0.35355339059327373f * e2 * (2.0f - r);
    float R21 = 0.2041241452319315f  * e2 * r;

    float rho3 = (2.0f / 3.0f) * r;
    float R30 = 0.1283000598199168f   * e3 * (3.0f - 3.0f * rho3 + 0.5f * rho3 * rho3);
    float R31 = 0.045360921162019494f * e3 * rho3 * (4.0f - rho3);
    float R32 = 0.02028602242947916f  * e3 * rho3 * rho3;

    float rho4 = 0.5f * r;
    float R40 = 0.0625f * e4 *
                (4.0f - 6.0f * rho4 + 2.0f * rho4 * rho4 - rho4 * rho4 * rho4 * (1.0f / 6.0f));
    float R41 = 0.016137430609197573f * e4 * rho4 * (10.0f - 5.0f * rho4 + 0.5f * rho4 * rho4);
    float R42 = 0.004658474194686761f * e4 * rho4 * rho4 * (6.0f - rho4);

    float v[NBASIS];
    v[0]  = R10 * C00;
    v[1]  = R20 * C00;
    v[2]  = R21 * Y1m1;  v[3]  = R21 * Y10;  v[4]  = R21 * Y1p1;
    v[5]  = R30 * C00;
    v[6]  = R31 * Y1m1;  v[7]  = R31 * Y10;  v[8]  = R31 * Y1p1;
    v[9]  = R32 * Y2m2;  v[10] = R32 * Y2m1; v[11] = R32 * Y20;
    v[12] = R32 * Y2p1;  v[13] = R32 * Y2p2;
    v[14] = R40 * C00;
    v[15] = R41 * Y1m1;  v[16] = R41 * Y10;  v[17] = R41 * Y1p1;
    v[18] = R42 * Y2m2;  v[19] = R42 * Y2m1; v[20] = R42 * Y20;
    v[21] = R42 * Y2p1;  v[22] = R42 * Y2p2;

#pragma unroll
    for (int k = 0; k < NBASIS; k++) g_poly[k * NPTS + p] = v[k];
}

// ---------------------------------------------------------------------------
// Kernel 2: out(4096 x 32768) = coeff(4096 x 23) @ poly(23 x 32768)
// f32x2 GEMM. Each thread: 4 consecutive output columns (poly in 46 float2
// regs). Coefficients staged in smem as duplicated {c,c} pairs, padded to 24
// pairs/row, and fetched TWO pairs per LDS.128 -> 12 shared loads per row
// instead of 23 (halves L1TEX pressure, which co-bound with fma last round).
// Output stored with __stcs (streaming) to keep poly resident in L2.
// ---------------------------------------------------------------------------
#define TPB   256
#define PT    1024   // points per block  (TPB * 4)
#define RT    128    // coefficient rows per block
#define CPAD  24     // pairs per row in smem (23 real + 1 zero pad)

__device__ __forceinline__ float2 fma2(float2 a, float2 b, float2 c) {
    unsigned long long ua, ub, uc;
    memcpy(&ua, &a, 8); memcpy(&ub, &b, 8); memcpy(&uc, &c, 8);
    asm("fma.rn.f32x2 %0, %1, %2, %0;" : "+l"(uc) : "l"(ua), "l"(ub));
    float2 d; memcpy(&d, &uc, 8);
    return d;
}

__global__ __launch_bounds__(TPB, 2) void gemm_kernel(const float* __restrict__ coeff,
                                                      float* __restrict__ out) {
    __shared__ float2 cs[RT * CPAD];   // 24 KB

    int tid = threadIdx.x;
    int p0  = blockIdx.x * PT + tid * 4;
    int r0  = blockIdx.y * RT;

    // Stage coefficient tile: duplicated pairs {c,c}, row padded to 24 pairs.
    for (int i = tid; i < RT * CPAD; i += TPB) {
        int rr = i / CPAD;
        int k  = i - rr * CPAD;
        float c = (k < NBASIS) ? coeff[(r0 + rr) * NBASIS + k] : 0.0f;
        cs[i] = make_float2(c, c);
    }

    // Poly columns for this thread's 4 points, split into aligned f32x2 pairs.
    float2 pxy[NBASIS], pzw[NBASIS];
#pragma unroll
    for (int k = 0; k < NBASIS; k++) {
        float4 t = *reinterpret_cast<const float4*>(&g_poly[k * NPTS + p0]);
        pxy[k] = make_float2(t.x, t.y);
        pzw[k] = make_float2(t.z, t.w);
    }
    __syncthreads();

    float* outp = out + (size_t)r0 * NPTS + p0;
    for (int rr = 0; rr < RT; ++rr) {
        const float4* crow = reinterpret_cast<const float4*>(cs + rr * CPAD);
        float2 a0 = make_float2(0.0f, 0.0f);
        float2 a1 = make_float2(0.0f, 0.0f);
#pragma unroll
        for (int q = 0; q < 11; q++) {           // pairs 0..21, 2 per LDS.128
            float4 c2 = crow[q];                 // broadcast, conflict-free
            float2 cA = make_float2(c2.x, c2.y);
            float2 cB = make_float2(c2.z, c2.w);
            a0 = fma2(cA, pxy[2 * q],     a0);
            a1 = fma2(cA, pzw[2 * q],     a1);
            a0 = fma2(cB, pxy[2 * q + 1], a0);
            a1 = fma2(cB, pzw[2 * q + 1], a1);
        }
        {                                        // pair 22 (last real one)
            float4 c2 = crow[11];
            float2 cA = make_float2(c2.x, c2.y);
            a0 = fma2(cA, pxy[22], a0);
            a1 = fma2(cA, pzw[22], a1);
        }
        float4 o = make_float4(a0.x, a0.y, a1.x, a1.y);
        __stcs(reinterpret_cast<float4*>(outp), o);   // streaming STG.128
        outp += NPTS;
    }
}

// ---------------------------------------------------------------------------
// Launch: [0] position (8*4096*3 f32), [1] coefficients (64*64*23 f32).
// Output: 64*64*8*4096 f32.
// ---------------------------------------------------------------------------
extern "C" void kernel_launch(void* const* d_in, const int* in_sizes, int n_in,
                              void* d_out, int out_size) {
    const float* pos   = (const float*)d_in[0];
    const float* coeff = (const float*)d_in[1];
    float* out = (float*)d_out;

    basis_kernel<<<NPTS / TPB, TPB>>>(pos);

    dim3 grid(NPTS / PT, NROWS / RT);   // (32, 32)
    gemm_kernel<<<grid, TPB>>>(coeff, out);
}